// round 13
// baseline (speedup 1.0000x reference)
#include <cuda_runtime.h>
#include <cuda_bf16.h>
#include <cstdint>

#define M_TOTAL 8192
#define KDIM    128
#define INVT    5.0f

// ---- device globals (no allocation allowed) -------------------------------
__device__ __align__(16) __nv_bfloat16 hiG[M_TOTAL * KDIM];
__device__ float    dG[M_TOTAL];
__device__ float    accG[M_TOTAL];
__device__ unsigned mG[M_TOTAL];
__device__ int      labG[M_TOTAL];
__device__ unsigned dminEnc = 0xFFFFFFFFu;   // encoded global min of dG (monotone across replays)
__device__ unsigned doneCtr = 0;             // wraps 4095 -> 0: self-resetting per replay

// ---- helpers --------------------------------------------------------------
__device__ __forceinline__ uint32_t smem_to_u32(const void* p) {
    uint32_t a;
    asm("{ .reg .u64 t; cvta.to.shared.u64 t, %1; cvt.u32.u64 %0, t; }" : "=r"(a) : "l"(p));
    return a;
}
__device__ __forceinline__ void cpa16(uint32_t dst, const void* src) {
    asm volatile("cp.async.cg.shared.global [%0], [%1], 16;" :: "r"(dst), "l"(src) : "memory");
}
__device__ __forceinline__ void ldsm4(uint32_t* r, uint32_t addr) {
    asm volatile("ldmatrix.sync.aligned.m8n8.x4.shared.b16 {%0,%1,%2,%3}, [%4];"
                 : "=r"(r[0]), "=r"(r[1]), "=r"(r[2]), "=r"(r[3]) : "r"(addr));
}
__device__ __forceinline__ void mma16816(float* c, const uint32_t* a, uint32_t b0, uint32_t b1) {
    asm volatile("mma.sync.aligned.m16n8k16.row.col.f32.bf16.bf16.f32 "
                 "{%0,%1,%2,%3}, {%4,%5,%6,%7}, {%8,%9}, {%0,%1,%2,%3};"
                 : "+f"(c[0]), "+f"(c[1]), "+f"(c[2]), "+f"(c[3])
                 : "r"(a[0]), "r"(a[1]), "r"(a[2]), "r"(a[3]), "r"(b0), "r"(b1));
}
// order-preserving float <-> unsigned (atomicMax/atomicMin on floats)
__device__ __forceinline__ unsigned fenc(float f) {
    unsigned u = __float_as_uint(f);
    return (u >> 31) ? ~u : (u | 0x80000000u);
}
__device__ __forceinline__ float fdec(unsigned e) {
    return (e >> 31) ? __uint_as_float(e & 0x7fffffffu) : __uint_as_float(~e);
}

// ---- kernel 1: bf16 cast, per-row norms, init (R5 config: 16 thr/row) ----
__global__ void __launch_bounds__(256)
prep_kernel(const float* __restrict__ feat, const long long* __restrict__ labels) {
    const int g   = blockIdx.x * 256 + threadIdx.x;
    const int row = g >> 4;
    const int sub = g & 15;               // 8 floats per thread
    const float4* src = reinterpret_cast<const float4*>(feat + (size_t)row * KDIM + sub * 8);
    float4 v0 = src[0], v1 = src[1];

    float ss = v0.x*v0.x + v0.y*v0.y + v0.z*v0.z + v0.w*v0.w
             + v1.x*v1.x + v1.y*v1.y + v1.z*v1.z + v1.w*v1.w;

    __nv_bfloat162 p0 = __floats2bfloat162_rn(v0.x, v0.y);
    __nv_bfloat162 p1 = __floats2bfloat162_rn(v0.z, v0.w);
    __nv_bfloat162 p2 = __floats2bfloat162_rn(v1.x, v1.y);
    __nv_bfloat162 p3 = __floats2bfloat162_rn(v1.z, v1.w);
    *reinterpret_cast<uint4*>(hiG + (size_t)row * KDIM + sub * 8) =
        make_uint4(*reinterpret_cast<uint32_t*>(&p0), *reinterpret_cast<uint32_t*>(&p1),
                   *reinterpret_cast<uint32_t*>(&p2), *reinterpret_cast<uint32_t*>(&p3));

    #pragma unroll
    for (int o = 8; o; o >>= 1) ss += __shfl_xor_sync(0xffffffffu, ss, o);
    if (sub == 0) {
        float d = ss * INVT;
        dG[row]   = d;
        accG[row] = 0.0f;
        mG[row]   = 0u;
        labG[row] = (int)labels[row];
        atomicMin(&dminEnc, fenc(d));
    }
}

// ---- kernel 2: symmetric HMMA GEMM (R8 core) + last-CTA final reduction --
// Tiles tj >= ti only. 128x128 tile, 8 warps (4x2), 32x64 micro-tile.

#define SMEM_A   0
#define SMEM_B   32768
#define SMEM_SZ  65536

__global__ void __launch_bounds__(256, 2)
main_kernel(float* __restrict__ out) {
    const int ti = blockIdx.y, tj = blockIdx.x;
    const int t = threadIdx.x;
    const int lane = t & 31, wid = t >> 5;

    if (tj >= ti) {
        const bool diag = (ti == tj);
        extern __shared__ char smem[];
        const uint32_t sb = smem_to_u32(smem);
        const int wm = wid & 3, wn = wid >> 2;
        const int rowbase = ti * 128;
        const int colbase = tj * 128;

        // ---- pipelined tile load: 4 k-chunks, uniform per-thread groups ----
        {
            const int qc = t & 3, rb = t >> 2;
            #pragma unroll
            for (int c = 0; c < 4; c++) {
                const int q = c * 4 + qc;
                const __nv_bfloat16* Ag = hiG + (size_t)(rowbase + rb) * KDIM + q * 8;
                const __nv_bfloat16* Bg = hiG + (size_t)(colbase + rb) * KDIM + q * 8;
                #pragma unroll
                for (int j = 0; j < 2; j++) {
                    const int row = rb + j * 64;
                    const uint32_t sw = (uint32_t)((q ^ (row & 7)) * 16);
                    cpa16(sb + SMEM_A + row * 256 + sw, Ag + (size_t)j * 64 * KDIM);
                    cpa16(sb + SMEM_B + row * 256 + sw, Bg + (size_t)j * 64 * KDIM);
                }
                asm volatile("cp.async.commit_group;" ::: "memory");
            }
        }

        // ---- GEMM, consuming k-chunks as they arrive ----
        float acc[2][8][4];
        #pragma unroll
        for (int mi = 0; mi < 2; mi++)
            #pragma unroll
            for (int bi = 0; bi < 8; bi++)
                #pragma unroll
                for (int rg = 0; rg < 4; rg++) acc[mi][bi][rg] = 0.f;

        #pragma unroll
        for (int c = 0; c < 4; c++) {
            switch (c) {
                case 0: asm volatile("cp.async.wait_group 3;" ::: "memory"); break;
                case 1: asm volatile("cp.async.wait_group 2;" ::: "memory"); break;
                case 2: asm volatile("cp.async.wait_group 1;" ::: "memory"); break;
                default: asm volatile("cp.async.wait_group 0;" ::: "memory"); break;
            }
            __syncthreads();
            #pragma unroll
            for (int kh = 0; kh < 2; kh++) {
                const int ks = c * 2 + kh;
                const int ql = ks * 2 + (lane >> 4);
                uint32_t af[2][4];
                #pragma unroll
                for (int mi = 0; mi < 2; mi++) {
                    int row = wm * 32 + mi * 16 + (lane & 15);
                    ldsm4(af[mi], sb + SMEM_A + row * 256 + ((ql ^ (row & 7)) * 16));
                }
                uint32_t bfm[4][4];
                #pragma unroll
                for (int bi = 0; bi < 4; bi++) {
                    int row = wn * 64 + bi * 16 + (lane & 15);
                    ldsm4(bfm[bi], sb + SMEM_B + row * 256 + ((ql ^ (row & 7)) * 16));
                }
                #pragma unroll
                for (int mi = 0; mi < 2; mi++)
                    #pragma unroll
                    for (int bi = 0; bi < 4; bi++) {
                        mma16816(acc[mi][bi * 2 + 0], af[mi], bfm[bi][0], bfm[bi][2]);
                        mma16816(acc[mi][bi * 2 + 1], af[mi], bfm[bi][1], bfm[bi][3]);
                    }
            }
        }

        // ---- row side: per-element FMAX only; exact deferred slow path ----
        #pragma unroll
        for (int s = 0; s < 4; s++) {
            const int gr = rowbase + wm * 32 + (s >> 1) * 16 + (s & 1) * 8 + (lane >> 2);
            float m = -1e30f;
            #pragma unroll
            for (int bi = 0; bi < 8; bi++) {
                m = fmaxf(m, acc[s >> 1][bi][(s & 1) * 2]);
                m = fmaxf(m, acc[s >> 1][bi][(s & 1) * 2 + 1]);
            }
            m = fmaxf(m, __shfl_xor_sync(0xffffffffu, m, 1));
            m = fmaxf(m, __shfl_xor_sync(0xffffffffu, m, 2));
            const float d = dG[gr];
            if (__builtin_expect(m * INVT - d > -75.f, 0)) {
                const int lr = labG[gr];
                #pragma unroll
                for (int bi = 0; bi < 8; bi++)
                    #pragma unroll
                    for (int rgl = 0; rgl < 2; rgl++) {
                        float sim = acc[s >> 1][bi][(s & 1) * 2 + rgl] * INVT;
                        float tt  = sim - d;
                        if (tt > -75.f) {
                            int c = colbase + wn * 64 + bi * 8 + (lane & 3) * 2 + rgl;
                            if (c != gr) {
                                float e = __expf(tt);
                                atomicAdd(&accG[gr], (lr == labG[c]) ? e : -e);
                            }
                        }
                    }
            }
            if ((lane & 3) == 0) atomicMax(&mG[gr], fenc(m * INVT));
        }

        // ---- col side (transposed contribution), off-diagonal tiles only ----
        if (!diag) {
            const float thrC = fdec(dminEnc) * 0.2f - 15.f;
            #pragma unroll
            for (int bi = 0; bi < 8; bi++)
                #pragma unroll
                for (int rgl = 0; rgl < 2; rgl++) {
                    float m = fmaxf(fmaxf(acc[0][bi][rgl], acc[0][bi][2 + rgl]),
                                    fmaxf(acc[1][bi][rgl], acc[1][bi][2 + rgl]));
                    m = fmaxf(m, __shfl_xor_sync(0xffffffffu, m, 4));
                    m = fmaxf(m, __shfl_xor_sync(0xffffffffu, m, 8));
                    m = fmaxf(m, __shfl_xor_sync(0xffffffffu, m, 16));
                    if (__builtin_expect(m > thrC, 0)) {
                        const int c  = colbase + wn * 64 + bi * 8 + (lane & 3) * 2 + rgl;
                        const float dc = dG[c];
                        const int lc = labG[c];
                        #pragma unroll
                        for (int mi = 0; mi < 2; mi++)
                            #pragma unroll
                            for (int rgh = 0; rgh < 2; rgh++) {
                                float sim = acc[mi][bi][rgh * 2 + rgl] * INVT;
                                float tt  = sim - dc;
                                if (tt > -75.f) {
                                    int r = rowbase + wm * 32 + mi * 16 + rgh * 8 + (lane >> 2);
                                    float e = __expf(tt);
                                    atomicAdd(&accG[c], (labG[r] == lc) ? e : -e);
                                }
                            }
                    }
                    if (lane < 4) {
                        int c = colbase + wn * 64 + bi * 8 + lane * 2 + rgl;
                        atomicMax(&mG[c], fenc(m * INVT));
                    }
                }
        }
    }

    // ---- last-CTA final reduction (all 4096 CTAs arrive here) ----
    __threadfence();
    __shared__ unsigned isLast;
    __shared__ double red[8];
    if (t == 0) {
        unsigned old = atomicInc(&doneCtr, 4095u);   // wraps to 0 after 4096 arrivals
        isLast = (old == 4095u) ? 1u : 0u;
    }
    __syncthreads();
    if (isLast) {
        __threadfence();
        double s = 0.0;
        #pragma unroll
        for (int i = 0; i < 32; i++) {
            int r = t + i * 256;
            float m = fdec(mG[r]);
            s += (double)(accG[r] * __expf(dG[r] - m));
        }
        #pragma unroll
        for (int o = 16; o; o >>= 1) s += __shfl_xor_sync(0xffffffffu, s, o);
        if (lane == 0) red[wid] = s;
        __syncthreads();
        if (wid == 0) {
            double v = (lane < 8) ? red[lane] : 0.0;
            #pragma unroll
            for (int o = 4; o; o >>= 1) v += __shfl_xor_sync(0xffffffffu, v, o);
            if (lane == 0) out[0] = (float)(-v / (double)M_TOTAL);
        }
    }
}

// ---- host ----------------------------------------------------------------
extern "C" void kernel_launch(void* const* d_in, const int* in_sizes, int n_in,
                              void* d_out, int out_size) {
    const float*     feat   = (const float*)d_in[0];
    const long long* labels = (const long long*)d_in[1];
    float* out = (float*)d_out;

    cudaFuncSetAttribute(main_kernel, cudaFuncAttributeMaxDynamicSharedMemorySize, SMEM_SZ);

    prep_kernel<<<M_TOTAL * 16 / 256, 256>>>(feat, labels);
    main_kernel<<<dim3(64, 64), 256, SMEM_SZ>>>(out);
}

// round 14
// speedup vs baseline: 1.5536x; 1.5536x over previous
#include <cuda_runtime.h>
#include <cuda_bf16.h>
#include <cstdint>

#define M_TOTAL 8192
#define KDIM    128
#define INVT    5.0f

// ---- device globals (no allocation allowed) -------------------------------
__device__ __align__(16) __nv_bfloat16 hiG[M_TOTAL * KDIM];
__device__ float    dG[M_TOTAL];
__device__ float    accG[M_TOTAL];
__device__ unsigned mG[M_TOTAL];
__device__ int      labG[M_TOTAL];
__device__ unsigned dminEnc = 0xFFFFFFFFu;   // encoded global min of dG

// ---- helpers --------------------------------------------------------------
__device__ __forceinline__ uint32_t smem_to_u32(const void* p) {
    uint32_t a;
    asm("{ .reg .u64 t; cvta.to.shared.u64 t, %1; cvt.u32.u64 %0, t; }" : "=r"(a) : "l"(p));
    return a;
}
__device__ __forceinline__ void cpa16(uint32_t dst, const void* src) {
    asm volatile("cp.async.cg.shared.global [%0], [%1], 16;" :: "r"(dst), "l"(src) : "memory");
}
__device__ __forceinline__ void ldsm4(uint32_t* r, uint32_t addr) {
    asm volatile("ldmatrix.sync.aligned.m8n8.x4.shared.b16 {%0,%1,%2,%3}, [%4];"
                 : "=r"(r[0]), "=r"(r[1]), "=r"(r[2]), "=r"(r[3]) : "r"(addr));
}
__device__ __forceinline__ void mma16816(float* c, const uint32_t* a, uint32_t b0, uint32_t b1) {
    asm volatile("mma.sync.aligned.m16n8k16.row.col.f32.bf16.bf16.f32 "
                 "{%0,%1,%2,%3}, {%4,%5,%6,%7}, {%8,%9}, {%0,%1,%2,%3};"
                 : "+f"(c[0]), "+f"(c[1]), "+f"(c[2]), "+f"(c[3])
                 : "r"(a[0]), "r"(a[1]), "r"(a[2]), "r"(a[3]), "r"(b0), "r"(b1));
}
// order-preserving float <-> unsigned (atomicMax/atomicMin on floats)
__device__ __forceinline__ unsigned fenc(float f) {
    unsigned u = __float_as_uint(f);
    return (u >> 31) ? ~u : (u | 0x80000000u);
}
__device__ __forceinline__ float fdec(unsigned e) {
    return (e >> 31) ? __uint_as_float(e & 0x7fffffffu) : __uint_as_float(~e);
}

// ---- kernel 1: bf16 cast, per-row norms, init ----------------------------
__global__ void __launch_bounds__(256)
prep_kernel(const float* __restrict__ feat, const long long* __restrict__ labels) {
    const int g   = blockIdx.x * 256 + threadIdx.x;
    const int row = g >> 4;
    const int sub = g & 15;               // 8 floats per thread
    const float4* src = reinterpret_cast<const float4*>(feat + (size_t)row * KDIM + sub * 8);
    float4 v0 = src[0], v1 = src[1];

    float ss = v0.x*v0.x + v0.y*v0.y + v0.z*v0.z + v0.w*v0.w
             + v1.x*v1.x + v1.y*v1.y + v1.z*v1.z + v1.w*v1.w;

    __nv_bfloat162 p0 = __floats2bfloat162_rn(v0.x, v0.y);
    __nv_bfloat162 p1 = __floats2bfloat162_rn(v0.z, v0.w);
    __nv_bfloat162 p2 = __floats2bfloat162_rn(v1.x, v1.y);
    __nv_bfloat162 p3 = __floats2bfloat162_rn(v1.z, v1.w);
    *reinterpret_cast<uint4*>(hiG + (size_t)row * KDIM + sub * 8) =
        make_uint4(*reinterpret_cast<uint32_t*>(&p0), *reinterpret_cast<uint32_t*>(&p1),
                   *reinterpret_cast<uint32_t*>(&p2), *reinterpret_cast<uint32_t*>(&p3));

    #pragma unroll
    for (int o = 8; o; o >>= 1) ss += __shfl_xor_sync(0xffffffffu, ss, o);
    if (sub == 0) {
        float d = ss * INVT;
        dG[row]   = d;
        accG[row] = 0.0f;
        mG[row]   = 0u;
        labG[row] = (int)labels[row];
        atomicMin(&dminEnc, fenc(d));
    }
}

// ---- kernel 2: symmetric HMMA GEMM, deferred-check dual-sided epilogue ---
// Tiles tj >= ti only. 128x128 tile, 8 warps (4x2), 32x64 micro-tile.

#define SMEM_A   0
#define SMEM_B   32768
#define SMEM_SZ  65536

__global__ void __launch_bounds__(256, 2)
main_kernel() {
    const int ti = blockIdx.y, tj = blockIdx.x;
    if (tj < ti) return;
    const bool diag = (ti == tj);

    extern __shared__ char smem[];
    const uint32_t sb = smem_to_u32(smem);
    const int t = threadIdx.x;
    const int lane = t & 31, wid = t >> 5;
    const int wm = wid & 3, wn = wid >> 2;
    const int rowbase = ti * 128;
    const int colbase = tj * 128;

    // ---- load A (rows) and B (cols) tiles, swizzled for ldmatrix ----
    {
        const int q = t & 15, r0 = t >> 4;
        const uint32_t sw = (uint32_t)((q ^ (r0 & 7)) * 16);
        const __nv_bfloat16* Ag = hiG + (size_t)(rowbase + r0) * KDIM + q * 8;
        const __nv_bfloat16* Bg = hiG + (size_t)(colbase + r0) * KDIM + q * 8;
        #pragma unroll
        for (int j = 0; j < 8; j++) {
            cpa16(sb + SMEM_A + (r0 + j * 16) * 256 + sw, Ag + (size_t)j * 16 * KDIM);
            cpa16(sb + SMEM_B + (r0 + j * 16) * 256 + sw, Bg + (size_t)j * 16 * KDIM);
        }
    }
    asm volatile("cp.async.commit_group;" ::: "memory");
    asm volatile("cp.async.wait_group 0;" ::: "memory");
    __syncthreads();

    // ---- GEMM ----
    float acc[2][8][4];
    #pragma unroll
    for (int mi = 0; mi < 2; mi++)
        #pragma unroll
        for (int bi = 0; bi < 8; bi++)
            #pragma unroll
            for (int rg = 0; rg < 4; rg++) acc[mi][bi][rg] = 0.f;

    #pragma unroll
    for (int ks = 0; ks < 8; ks++) {
        uint32_t af[2][4];
        #pragma unroll
        for (int mi = 0; mi < 2; mi++) {
            int row = wm * 32 + mi * 16 + (lane & 15);
            int ql  = ks * 2 + (lane >> 4);
            ldsm4(af[mi], sb + SMEM_A + row * 256 + ((ql ^ (row & 7)) * 16));
        }
        uint32_t bfm[4][4];
        #pragma unroll
        for (int bi = 0; bi < 4; bi++) {
            int row = wn * 64 + bi * 16 + (lane & 15);
            int ql  = ks * 2 + (lane >> 4);
            ldsm4(bfm[bi], sb + SMEM_B + row * 256 + ((ql ^ (row & 7)) * 16));
        }
        #pragma unroll
        for (int mi = 0; mi < 2; mi++)
            #pragma unroll
            for (int bi = 0; bi < 4; bi++) {
                mma16816(acc[mi][bi * 2 + 0], af[mi], bfm[bi][0], bfm[bi][2]);
                mma16816(acc[mi][bi * 2 + 1], af[mi], bfm[bi][1], bfm[bi][3]);
            }
    }

    // ---- row side: per-element FMAX only; exact deferred slow path ----
    #pragma unroll
    for (int s = 0; s < 4; s++) {
        const int gr = rowbase + wm * 32 + (s >> 1) * 16 + (s & 1) * 8 + (lane >> 2);
        float m = -1e30f;
        #pragma unroll
        for (int bi = 0; bi < 8; bi++) {
            m = fmaxf(m, acc[s >> 1][bi][(s & 1) * 2]);
            m = fmaxf(m, acc[s >> 1][bi][(s & 1) * 2 + 1]);
        }
        m = fmaxf(m, __shfl_xor_sync(0xffffffffu, m, 1));
        m = fmaxf(m, __shfl_xor_sync(0xffffffffu, m, 2));     // row max (raw s), all lanes
        const float d = dG[gr];
        if (__builtin_expect(m * INVT - d > -75.f, 0)) {
            // exact slow path: rescan this lane's 16 elements of row gr
            const int lr = labG[gr];
            #pragma unroll
            for (int bi = 0; bi < 8; bi++)
                #pragma unroll
                for (int rgl = 0; rgl < 2; rgl++) {
                    float sim = acc[s >> 1][bi][(s & 1) * 2 + rgl] * INVT;
                    float tt  = sim - d;
                    if (tt > -75.f) {
                        int c = colbase + wn * 64 + bi * 8 + (lane & 3) * 2 + rgl;
                        if (c != gr) {
                            float e = __expf(tt);
                            atomicAdd(&accG[gr], (lr == labG[c]) ? e : -e);
                        }
                    }
                }
        }
        if ((lane & 3) == 0) atomicMax(&mG[gr], fenc(m * INVT));
    }

    // ---- col side (transposed contribution), off-diagonal tiles only ----
    if (!diag) {
        const float thrC = fdec(dminEnc) * 0.2f - 15.f;   // conservative raw-s threshold
        #pragma unroll
        for (int bi = 0; bi < 8; bi++)
            #pragma unroll
            for (int rgl = 0; rgl < 2; rgl++) {
                float m = fmaxf(fmaxf(acc[0][bi][rgl], acc[0][bi][2 + rgl]),
                                fmaxf(acc[1][bi][rgl], acc[1][bi][2 + rgl]));
                m = fmaxf(m, __shfl_xor_sync(0xffffffffu, m, 4));
                m = fmaxf(m, __shfl_xor_sync(0xffffffffu, m, 8));
                m = fmaxf(m, __shfl_xor_sync(0xffffffffu, m, 16));  // col max, all lanes
                if (__builtin_expect(m > thrC, 0)) {
                    // exact slow path for this lane's column
                    const int c  = colbase + wn * 64 + bi * 8 + (lane & 3) * 2 + rgl;
                    const float dc = dG[c];
                    const int lc = labG[c];
                    #pragma unroll
                    for (int mi = 0; mi < 2; mi++)
                        #pragma unroll
                        for (int rgh = 0; rgh < 2; rgh++) {
                            float sim = acc[mi][bi][rgh * 2 + rgl] * INVT;
                            float tt  = sim - dc;
                            if (tt > -75.f) {
                                int r = rowbase + wm * 32 + mi * 16 + rgh * 8 + (lane >> 2);
                                float e = __expf(tt);
                                atomicAdd(&accG[c], (labG[r] == lc) ? e : -e);
                            }
                        }
                }
                if (lane < 4) {
                    int c = colbase + wn * 64 + bi * 8 + lane * 2 + rgl;
                    atomicMax(&mG[c], fenc(m * INVT));
                }
            }
    }
}

// ---- kernel 3: exact max rebase + mean -----------------------------------
__global__ void final_kernel(float* __restrict__ out) {
    __shared__ double red[32];
    const int t = threadIdx.x, lane = t & 31, warp = t >> 5;
    double s = 0.0;
    #pragma unroll
    for (int i = 0; i < 8; i++) {
        int r = t + i * 1024;
        float m = fdec(mG[r]);
        s += (double)(accG[r] * __expf(dG[r] - m));
    }
    #pragma unroll
    for (int o = 16; o; o >>= 1) s += __shfl_xor_sync(0xffffffffu, s, o);
    if (lane == 0) red[warp] = s;
    __syncthreads();
    if (warp == 0) {
        double v = red[lane];
        #pragma unroll
        for (int o = 16; o; o >>= 1) v += __shfl_xor_sync(0xffffffffu, v, o);
        if (lane == 0) out[0] = (float)(-v / (double)M_TOTAL);
    }
}

// ---- host ----------------------------------------------------------------
extern "C" void kernel_launch(void* const* d_in, const int* in_sizes, int n_in,
                              void* d_out, int out_size) {
    const float*     feat   = (const float*)d_in[0];
    const long long* labels = (const long long*)d_in[1];
    float* out = (float*)d_out;

    cudaFuncSetAttribute(main_kernel, cudaFuncAttributeMaxDynamicSharedMemorySize, SMEM_SZ);

    prep_kernel<<<M_TOTAL * 16 / 256, 256>>>(feat, labels);
    main_kernel<<<dim3(64, 64), 256, SMEM_SZ>>>();
    final_kernel<<<1, 1024>>>(out);
}